// round 14
// baseline (speedup 1.0000x reference)
#include <cuda_runtime.h>
#include <stdint.h>

#define BATCH 128
#define NANCH 16800
#define NQ 4200               // float4 per row
#define T 1024
#define NW 32
#define NIT 5                 // ceil(NQ / T)
#define NEG_RATIO 3
#define SCALE_XY 10.0f
#define SCALE_WH 5.0f
#define SEG 128               // per-warp buffer entries (exp ~80, 5.8 sigma)
#define XCF 1.1f              // x cutoff (softplus monotone; K-th x ~1.55)
#define HBSHIFT 13
#define HBINS 4096            // bins over x in [1.0, 16.0)
#define HBASE (0x3F800000u >> HBSHIFT)
#define CHB 4                 // HBINS / T
#define TIE_CAP 64
#define TAG 0x80000000u
#define FLT_EPS_ 1.1920929e-07f

// Cross-block scratch (allocation-free rule: __device__ globals)
__device__ float g_row_lossb[BATCH];
__device__ float g_row_lossl[BATCH];
__device__ int   g_row_posn[BATCH];
__device__ int   g_done = 0;

__device__ __forceinline__ float warp_sum(float v) {
    #pragma unroll
    for (int o = 16; o > 0; o >>= 1) v += __shfl_down_sync(0xFFFFFFFFu, v, o);
    return v;
}
__device__ __forceinline__ int warp_sum_i(int v) {
    #pragma unroll
    for (int o = 16; o > 0; o >>= 1) v += __shfl_down_sync(0xFFFFFFFFu, v, o);
    return v;
}
__device__ __forceinline__ int warp_suffix_incl_i(int v, int lane) {
    #pragma unroll
    for (int o = 1; o < 32; o <<= 1) {
        int u = __shfl_down_sync(0xFFFFFFFFu, v, o);
        if (lane + o < 32) v += u;
    }
    return v;
}
__device__ __forceinline__ float bce_of(float x, float y) {
    return fmaxf(x, 0.f) - x * y + __logf(1.f + __expf(-fabsf(x)));
}
__device__ __forceinline__ float softplus_pos(float x) {   // bce for negative, x>0
    return x + __logf(1.f + __expf(-x));
}
__device__ __forceinline__ unsigned fmap(unsigned b) {     // order-preserving signed map
    return (b & 0x80000000u) ? ~b : (b | 0x80000000u);
}

__global__ __launch_bounds__(T, 1)
void od_fused(const float* __restrict__ pbboxs,
              const float* __restrict__ plabels,
              const float* __restrict__ gbboxs,
              const float* __restrict__ glabels,
              const float* __restrict__ ancs,
              float* __restrict__ out, int out_size) {
    const int b    = blockIdx.x;
    const int tid  = threadIdx.x;
    const int lane = tid & 31;
    const int wid  = tid >> 5;

    __shared__ unsigned s_buf[NW * SEG];   // per-warp tagged streams (16 KB)
    __shared__ int      s_hist[HBINS];     // 16 KB
    __shared__ unsigned s_tie[TIE_CAP];
    __shared__ int      s_wcnt[NW];
    __shared__ float    s_wf[NW], s_wf2[NW];
    __shared__ int      s_wi[NW], s_wsuf[NW], s_wi2[NW];
    __shared__ float    s_sl1, s_bce, s_top;
    __shared__ int      s_ovf, s_tn, s_tbin, s_last;
    __shared__ unsigned s_lo, s_hi;
    __shared__ float    s_red[NW * 3];

    #pragma unroll
    for (int j = 0; j < CHB; j++) s_hist[tid + j * T] = 0;
    if (tid == 0) { s_ovf = 0; s_tn = 0; s_top = 0.f; s_tbin = 0; }
    __syncthreads();

    const float*  plr = plabels + (size_t)b * NANCH;
    const float*  glr = glabels + (size_t)b * NANCH;
    const float4* pl4 = (const float4*)plr;
    const float4* gl4 = (const float4*)glr;
    const float4* pb  = (const float4*)pbboxs + (size_t)b * NANCH;
    const float4* gb  = (const float4*)gbboxs + (size_t)b * NANCH;
    const float4* an  = (const float4*)ancs;

    // ---- Prefetch ALL streaming loads (10 LDG.128 in flight per thread) ----
    float4 xv[NIT], yv[NIT];
    #pragma unroll
    for (int it = 0; it < NIT; it++) {
        const int i4 = tid + it * T;
        if (i4 < NQ) { xv[it] = pl4[i4]; yv[it] = gl4[i4]; }
        else { xv[it] = make_float4(0.f, 0.f, 0.f, 0.f); yv[it] = make_float4(0.f, 0.f, 0.f, 0.f); }
    }

    // ---- Main loop: compare + ballot + rare STS; NO atomics, NO shfl ----
    const unsigned lm = (1u << lane) - 1u;
    const unsigned wbase = wid * SEG;
    int wcount = 0;       // warp-uniform running count of this warp's entries
    bool ovf_local = false;
    #pragma unroll
    for (int it = 0; it < NIT; it++) {
        const int ei0 = (tid + it * T) << 2;
        #pragma unroll
        for (int c = 0; c < 4; c++) {
            float x = (c == 0) ? xv[it].x : (c == 1) ? xv[it].y : (c == 2) ? xv[it].z : xv[it].w;
            float y = (c == 0) ? yv[it].x : (c == 1) ? yv[it].y : (c == 2) ? yv[it].z : yv[it].w;
            const bool pos  = (y > 0.f);                    // tail: y=0 -> never
            const bool intr = pos | (x >= XCF);             // tail: x=0 -> never
            unsigned msk = __ballot_sync(0xFFFFFFFFu, intr);
            if (intr) {
                const unsigned val = pos ? (TAG | (unsigned)(ei0 + c))
                                         : __float_as_uint(x);
                const int pi = wcount + __popc(msk & lm);
                if (pi < SEG) s_buf[wbase + pi] = val;
                else ovf_local = true;
            }
            wcount += __popc(msk);
        }
    }
    if (lane == 0) {
        s_wcnt[wid] = wcount;
        if (wcount > SEG) s_ovf = 1;
    }
    if (ovf_local) s_ovf = 1;
    __syncthreads();

    // ---- Phase 2: each warp walks its own segment ----
    // tagged -> positive gather (batched); untagged -> histogram
    const int myn = (wcount < SEG) ? wcount : SEG;
    float acc_sl1 = 0.f, acc_bce = 0.f;
    int pcnt = 0, ccnt = 0;
    for (int idx = lane; idx < myn; idx += 32) {
        const unsigned u = s_buf[wbase + idx];
        if (u & TAG) {
            const int i = (int)(u & 0xFFFFu);
            float x = plr[i];
            float y = glr[i];
            acc_bce += bce_of(x, y);
            float4 p = pb[i];
            float4 g = gb[i];
            float4 a = an[i];
            float inv_az = 1.f / a.z;
            float inv_aw = 1.f / a.w;
            float d0 = p.x - SCALE_XY * (g.x - a.x) * inv_az;
            float d1 = p.y - SCALE_XY * (g.y - a.y) * inv_aw;
            float d2 = p.z - SCALE_WH * __logf(g.z * inv_az);
            float d3 = p.w - SCALE_WH * __logf(g.w * inv_aw);
            float ad;
            ad = fabsf(d0); acc_sl1 += (ad < 1.f) ? 0.5f * d0 * d0 : ad - 0.5f;
            ad = fabsf(d1); acc_sl1 += (ad < 1.f) ? 0.5f * d1 * d1 : ad - 0.5f;
            ad = fabsf(d2); acc_sl1 += (ad < 1.f) ? 0.5f * d2 * d2 : ad - 0.5f;
            ad = fabsf(d3); acc_sl1 += (ad < 1.f) ? 0.5f * d3 * d3 : ad - 0.5f;
            pcnt++;
        } else {
            unsigned bin = (u >> HBSHIFT) - HBASE;
            if (bin > HBINS - 1) bin = HBINS - 1;
            atomicAdd(&s_hist[bin], 1);   // spread addresses, cheap
            ccnt++;
        }
    }
    {
        float w1 = warp_sum(acc_sl1);
        float w2 = warp_sum(acc_bce);
        int   w3 = warp_sum_i(pcnt);
        int   w4 = warp_sum_i(ccnt);
        if (lane == 0) { s_wf[wid] = w1; s_wf2[wid] = w2; s_wi[wid] = w3; s_wi2[wid] = w4; }
    }
    __syncthreads();
    if (tid < 32) {
        float v1 = warp_sum(s_wf[lane]);
        float v2 = warp_sum(s_wf2[lane]);
        int   v3 = warp_sum_i(s_wi[lane]);
        int   v4 = warp_sum_i(s_wi2[lane]);
        if (lane == 0) { s_sl1 = v1; s_bce = v2; s_wi[0] = v3; s_wi2[0] = v4; }
    }
    __syncthreads();
    const int pos_num = s_wi[0];
    const int M       = s_wi2[0];
    const bool ovf    = (s_ovf != 0);
    __syncthreads();   // protect s_wi/s_wi2 reuse below

    int K = NEG_RATIO * pos_num;
    if (K > NANCH) K = NANCH;

    if (K > 0) {
        if (!ovf && M >= K) {
            // ---- Exact top-K: suffix-scan over the already-built histogram ----
            const int base = tid * CHB;
            int lc[CHB];
            int tot = 0;
            #pragma unroll
            for (int j = 0; j < CHB; j++) { lc[j] = s_hist[base + j]; tot += lc[j]; }
            int incl = warp_suffix_incl_i(tot, lane);
            if (lane == 0) s_wi[wid] = incl;
            __syncthreads();
            if (tid < 32) {
                int wv = s_wi[lane];
                int wi = warp_suffix_incl_i(wv, lane);
                s_wsuf[lane] = wi - wv;
            }
            __syncthreads();
            const int excl = (incl - tot) + s_wsuf[wid];
            if (excl < K && excl + tot >= K) {
                int cum = excl;
                #pragma unroll
                for (int j = CHB - 1; j >= 0; j--) {
                    cum += lc[j];
                    if (cum >= K) { s_tbin = base + j; break; }
                }
            }
            __syncthreads();
            const int tbin = s_tbin;

            // exact: softplus-sum above tie bin (walk own segment); gather ties
            float sa = 0.f;
            int ca = 0;
            for (int idx = lane; idx < myn; idx += 32) {
                const unsigned u = s_buf[wbase + idx];
                if (!(u & TAG)) {
                    int bin = (int)((u >> HBSHIFT) - HBASE);
                    if (bin > HBINS - 1) bin = HBINS - 1;
                    if (bin > tbin) { sa += softplus_pos(__uint_as_float(u)); ca++; }
                    else if (bin == tbin) {
                        int pi = atomicAdd(&s_tn, 1);
                        if (pi < TIE_CAP) s_tie[pi] = u;
                    }
                }
            }
            sa = warp_sum(sa);
            ca = warp_sum_i(ca);
            if (lane == 0) { s_wf[wid] = sa; s_wi[wid] = ca; }
            __syncthreads();
            if (tid == 0) {
                float fs = 0.f; int cs = 0;
                #pragma unroll
                for (int i = 0; i < NW; i++) { fs += s_wf[i]; cs += s_wi[i]; }
                int kr = K - cs;
                const int tn = s_tn;
                float tadd = 0.f;
                if (kr > 0) {
                    if (tn <= TIE_CAP) {
                        for (int a2 = 0; a2 < kr; a2++) {   // exact top-kr of tiny tie set
                            int mi = a2;
                            for (int z = a2 + 1; z < tn; z++)
                                if (s_tie[z] > s_tie[mi]) mi = z;
                            unsigned tv = s_tie[mi];
                            s_tie[mi] = s_tie[a2];
                            s_tie[a2] = tv;
                            tadd += softplus_pos(__uint_as_float(tv));
                        }
                    } else {
                        float ts = 0.f;
                        for (int z = 0; z < TIE_CAP; z++) ts += softplus_pos(__uint_as_float(s_tie[z]));
                        tadd = (float)kr * (ts / (float)TIE_CAP);
                    }
                }
                s_top = fs + tadd;
            }
            __syncthreads();
        } else {
            // ---- Exact fallback: binary search on mapped x-bits (never taken) ----
            int K_eff = NANCH - pos_num;
            if (K < K_eff) K_eff = K;
            if (K_eff > 0) {
                if (tid == 0) { s_lo = 0u; s_hi = 0xFFFFFFFFu; }
                __syncthreads();
                for (int s = 0; s < 64; s++) {
                    const unsigned lo = s_lo, hi = s_hi;
                    const unsigned w = hi - lo;
                    if (w <= 1u) break;
                    const unsigned bmid = lo + (w >> 1);
                    int c1 = 0;
                    for (int i4 = tid; i4 < NQ; i4 += T) {
                        float4 xq = pl4[i4];
                        float4 yq = gl4[i4];
                        #pragma unroll
                        for (int c = 0; c < 4; c++) {
                            float x = (c == 0) ? xq.x : (c == 1) ? xq.y : (c == 2) ? xq.z : xq.w;
                            float y = (c == 0) ? yq.x : (c == 1) ? yq.y : (c == 2) ? yq.z : yq.w;
                            if (!(y > 0.f)) c1 += (fmap(__float_as_uint(x)) >= bmid);
                        }
                    }
                    c1 = warp_sum_i(c1);
                    if (lane == 0) s_wi[wid] = c1;
                    __syncthreads();
                    if (tid == 0) {
                        int t = 0;
                        #pragma unroll
                        for (int i = 0; i < NW; i++) t += s_wi[i];
                        if (t >= K_eff) s_lo = bmid; else s_hi = bmid;
                    }
                    __syncthreads();
                }
                const unsigned lo = s_lo;
                float sa = 0.f;
                int ca = 0;
                for (int i4 = tid; i4 < NQ; i4 += T) {
                    float4 xq = pl4[i4];
                    float4 yq = gl4[i4];
                    #pragma unroll
                    for (int c = 0; c < 4; c++) {
                        float x = (c == 0) ? xq.x : (c == 1) ? xq.y : (c == 2) ? xq.z : xq.w;
                        float y = (c == 0) ? yq.x : (c == 1) ? yq.y : (c == 2) ? yq.z : yq.w;
                        if (!(y > 0.f) && fmap(__float_as_uint(x)) > lo) { sa += bce_of(x, 0.f); ca++; }
                    }
                }
                sa = warp_sum(sa);
                ca = warp_sum_i(ca);
                if (lane == 0) { s_wf[wid] = sa; s_wi[wid] = ca; }
                __syncthreads();
                if (tid == 0) {
                    float fs = 0.f; int cs = 0;
                    #pragma unroll
                    for (int i = 0; i < NW; i++) { fs += s_wf[i]; cs += s_wi[i]; }
                    float xlo = (lo & 0x80000000u) ? __uint_as_float(lo & 0x7FFFFFFFu)
                                                   : __uint_as_float(~lo);
                    s_top = fs + (float)(K_eff - cs) * bce_of(xlo, 0.f);
                }
                __syncthreads();
            }
        }
    }
    const float sum_top = (K > 0) ? s_top : 0.f;

    // ---- Publish row; last block does the final reduction ----
    if (tid == 0) {
        g_row_posn[b]  = pos_num;
        g_row_lossb[b] = s_sl1;
        g_row_lossl[b] = s_bce + sum_top;
        __threadfence();
        int prev = atomicAdd(&g_done, 1);
        s_last = (prev == BATCH - 1);
    }
    __syncthreads();

    if (s_last) {
        float vlb = 0.f, vll = 0.f, vm = 0.f;
        if (tid < BATCH) {
            float pn  = (float)((volatile int*)g_row_posn)[tid];
            float lbv = ((volatile float*)g_row_lossb)[tid];
            float llv = ((volatile float*)g_row_lossl)[tid];
            float mask = (pn > 0.f) ? 1.f : 0.f;
            float wgt  = mask / fmaxf(pn, FLT_EPS_);
            vlb = lbv * wgt;
            vll = llv * wgt;
            vm  = wgt;
        }
        vlb = warp_sum(vlb);
        vll = warp_sum(vll);
        vm  = warp_sum(vm);
        if (lane == 0) {
            s_red[wid * 3 + 0] = vlb;
            s_red[wid * 3 + 1] = vll;
            s_red[wid * 3 + 2] = vm;
        }
        __syncthreads();
        if (tid == 0) {
            float slb = 0.f, sll = 0.f, sm = 0.f;
            #pragma unroll
            for (int w = 0; w < NW; w++) {
                slb += s_red[w * 3 + 0];
                sll += s_red[w * 3 + 1];
                sm  += s_red[w * 3 + 2];
            }
            const float lb = slb / (float)BATCH;
            const float ll = sll / (float)BATCH;
            const float total = (lb + ll) * (sm / (float)BATCH);
            if (out_size >= 1) out[0] = total;
            if (out_size >= 2) out[1] = lb;
            if (out_size >= 3) out[2] = ll;
            g_done = 0;  // reset for next graph replay
        }
    }
}

extern "C" void kernel_launch(void* const* d_in, const int* in_sizes, int n_in,
                              void* d_out, int out_size) {
    const float* pbboxs  = (const float*)d_in[0];
    const float* plabels = (const float*)d_in[1];
    const float* gbboxs  = (const float*)d_in[2];
    const float* glabels = (const float*)d_in[3];
    const float* ancs    = (const float*)d_in[4];
    (void)in_sizes; (void)n_in;

    od_fused<<<BATCH, T>>>(pbboxs, plabels, gbboxs, glabels, ancs,
                           (float*)d_out, out_size);
}

// round 15
// speedup vs baseline: 1.0325x; 1.0325x over previous
#include <cuda_runtime.h>
#include <stdint.h>

#define BATCH 128
#define NANCH 16800
#define NQ 4200               // float4 per row
#define T 1024
#define NW 32
#define NIT 5                 // ceil(NQ / T)
#define NEG_RATIO 3
#define SCALE_XY 10.0f
#define SCALE_WH 5.0f
#define SEG 128               // per-warp buffer entries (exp ~80, 5.8 sigma)
#define XCF 1.1f              // x cutoff (softplus monotone; K-th x ~1.55)
#define HBSHIFT 13
#define HBINS 4096            // bins over x in [1.0, 16.0)
#define HBASE (0x3F800000u >> HBSHIFT)
#define CHB 4                 // HBINS / T
#define TIE_CAP 64
#define TAG 0x80000000u
#define FLT_EPS_ 1.1920929e-07f

// Cross-block scratch (allocation-free rule: __device__ globals)
__device__ float g_row_lossb[BATCH];
__device__ float g_row_lossl[BATCH];
__device__ int   g_row_posn[BATCH];
__device__ int   g_done = 0;

__device__ __forceinline__ float warp_sum(float v) {
    #pragma unroll
    for (int o = 16; o > 0; o >>= 1) v += __shfl_down_sync(0xFFFFFFFFu, v, o);
    return v;
}
__device__ __forceinline__ int warp_sum_i(int v) {
    #pragma unroll
    for (int o = 16; o > 0; o >>= 1) v += __shfl_down_sync(0xFFFFFFFFu, v, o);
    return v;
}
__device__ __forceinline__ int warp_suffix_incl_i(int v, int lane) {
    #pragma unroll
    for (int o = 1; o < 32; o <<= 1) {
        int u = __shfl_down_sync(0xFFFFFFFFu, v, o);
        if (lane + o < 32) v += u;
    }
    return v;
}
__device__ __forceinline__ float bce_of(float x, float y) {
    return fmaxf(x, 0.f) - x * y + __logf(1.f + __expf(-fabsf(x)));
}
__device__ __forceinline__ float softplus_pos(float x) {   // bce for negative, x>0
    return x + __logf(1.f + __expf(-x));
}
__device__ __forceinline__ unsigned fmap(unsigned b) {     // order-preserving signed map
    return (b & 0x80000000u) ? ~b : (b | 0x80000000u);
}

__global__ __launch_bounds__(T, 1)
void od_fused(const float* __restrict__ pbboxs,
              const float* __restrict__ plabels,
              const float* __restrict__ gbboxs,
              const float* __restrict__ glabels,
              const float* __restrict__ ancs,
              float* __restrict__ out, int out_size) {
    const int b    = blockIdx.x;
    const int tid  = threadIdx.x;
    const int lane = tid & 31;
    const int wid  = tid >> 5;

    __shared__ unsigned s_buf[NW * SEG];   // per-warp tagged streams (16 KB)
    __shared__ int      s_hist[HBINS];     // 16 KB
    __shared__ unsigned s_tie[TIE_CAP];
    __shared__ float    s_wf[NW], s_wf2[NW];
    __shared__ int      s_wi[NW], s_wsuf[NW], s_wi2[NW];
    __shared__ float    s_sl1, s_bce, s_top;
    __shared__ int      s_ovf, s_tn, s_tbin, s_last;
    __shared__ unsigned s_lo, s_hi;
    __shared__ float    s_red[NW * 3];

    #pragma unroll
    for (int j = 0; j < CHB; j++) s_hist[tid + j * T] = 0;
    if (tid == 0) { s_ovf = 0; s_tn = 0; s_top = 0.f; s_tbin = 0; }
    __syncthreads();

    const float*  plr = plabels + (size_t)b * NANCH;
    const float*  glr = glabels + (size_t)b * NANCH;
    const float4* pl4 = (const float4*)plr;
    const float4* gl4 = (const float4*)glr;
    const float4* pb  = (const float4*)pbboxs + (size_t)b * NANCH;
    const float4* gb  = (const float4*)gbboxs + (size_t)b * NANCH;
    const float4* an  = (const float4*)ancs;

    // ---- Main loop: double-buffered loads; compare + ballot + rare STS ----
    // (no atomics, no shfl-broadcasts, 4 ballots/iter)
    const unsigned lm = (1u << lane) - 1u;
    const unsigned wbase = wid * SEG;
    int wcount = 0;       // warp-uniform running count of this warp's entries
    bool ovf_local = false;

    float4 xv = make_float4(0.f, 0.f, 0.f, 0.f);
    float4 yv = make_float4(0.f, 0.f, 0.f, 0.f);
    if (tid < NQ) { xv = pl4[tid]; yv = gl4[tid]; }
    #pragma unroll
    for (int it = 0; it < NIT; it++) {
        float4 xn = make_float4(0.f, 0.f, 0.f, 0.f);
        float4 yn = make_float4(0.f, 0.f, 0.f, 0.f);
        if (it + 1 < NIT) {
            const int i4n = tid + (it + 1) * T;
            if (i4n < NQ) { xn = pl4[i4n]; yn = gl4[i4n]; }
        }
        const int ei0 = (tid + it * T) << 2;
        #pragma unroll
        for (int c = 0; c < 4; c++) {
            float x = (c == 0) ? xv.x : (c == 1) ? xv.y : (c == 2) ? xv.z : xv.w;
            float y = (c == 0) ? yv.x : (c == 1) ? yv.y : (c == 2) ? yv.z : yv.w;
            const bool pos  = (y > 0.f);           // tail: y=0 -> never
            const bool intr = pos | (x >= XCF);    // tail: x=0 -> never
            unsigned msk = __ballot_sync(0xFFFFFFFFu, intr);
            if (intr) {
                const unsigned val = pos ? (TAG | (unsigned)(ei0 + c))
                                         : __float_as_uint(x);
                const int pi = wcount + __popc(msk & lm);
                if (pi < SEG) s_buf[wbase + pi] = val;
                else ovf_local = true;
            }
            wcount += __popc(msk);
        }
        xv = xn; yv = yn;
    }
    if ((lane == 0 && wcount > SEG) || ovf_local) s_ovf = 1;
    __syncthreads();

    // ---- Phase 2: each warp walks its own segment ----
    // tagged -> positive gather (batched); untagged -> histogram
    const int myn = (wcount < SEG) ? wcount : SEG;
    float acc_sl1 = 0.f, acc_bce = 0.f;
    int pcnt = 0, ccnt = 0;
    for (int idx = lane; idx < myn; idx += 32) {
        const unsigned u = s_buf[wbase + idx];
        if (u & TAG) {
            const int i = (int)(u & 0xFFFFu);
            float x = plr[i];
            float y = glr[i];
            acc_bce += bce_of(x, y);
            float4 p = pb[i];
            float4 g = gb[i];
            float4 a = an[i];
            float inv_az = 1.f / a.z;
            float inv_aw = 1.f / a.w;
            float d0 = p.x - SCALE_XY * (g.x - a.x) * inv_az;
            float d1 = p.y - SCALE_XY * (g.y - a.y) * inv_aw;
            float d2 = p.z - SCALE_WH * __logf(g.z * inv_az);
            float d3 = p.w - SCALE_WH * __logf(g.w * inv_aw);
            float ad;
            ad = fabsf(d0); acc_sl1 += (ad < 1.f) ? 0.5f * d0 * d0 : ad - 0.5f;
            ad = fabsf(d1); acc_sl1 += (ad < 1.f) ? 0.5f * d1 * d1 : ad - 0.5f;
            ad = fabsf(d2); acc_sl1 += (ad < 1.f) ? 0.5f * d2 * d2 : ad - 0.5f;
            ad = fabsf(d3); acc_sl1 += (ad < 1.f) ? 0.5f * d3 * d3 : ad - 0.5f;
            pcnt++;
        } else {
            unsigned bin = (u >> HBSHIFT) - HBASE;
            if (bin > HBINS - 1) bin = HBINS - 1;
            atomicAdd(&s_hist[bin], 1);   // spread addresses, cheap
            ccnt++;
        }
    }
    {
        float w1 = warp_sum(acc_sl1);
        float w2 = warp_sum(acc_bce);
        int   w3 = warp_sum_i(pcnt);
        int   w4 = warp_sum_i(ccnt);
        if (lane == 0) { s_wf[wid] = w1; s_wf2[wid] = w2; s_wi[wid] = w3; s_wi2[wid] = w4; }
    }
    __syncthreads();
    if (tid < 32) {
        float v1 = warp_sum(s_wf[lane]);
        float v2 = warp_sum(s_wf2[lane]);
        int   v3 = warp_sum_i(s_wi[lane]);
        int   v4 = warp_sum_i(s_wi2[lane]);
        if (lane == 0) { s_sl1 = v1; s_bce = v2; s_wi[0] = v3; s_wi2[0] = v4; }
    }
    __syncthreads();
    const int pos_num = s_wi[0];
    const int M       = s_wi2[0];
    const bool ovf    = (s_ovf != 0);
    __syncthreads();   // protect s_wi/s_wi2 reuse below

    int K = NEG_RATIO * pos_num;
    if (K > NANCH) K = NANCH;

    if (K > 0) {
        if (!ovf && M >= K) {
            // ---- Exact top-K: suffix-scan over the already-built histogram ----
            const int base = tid * CHB;
            int lc[CHB];
            int tot = 0;
            #pragma unroll
            for (int j = 0; j < CHB; j++) { lc[j] = s_hist[base + j]; tot += lc[j]; }
            int incl = warp_suffix_incl_i(tot, lane);
            if (lane == 0) s_wi[wid] = incl;
            __syncthreads();
            if (tid < 32) {
                int wv = s_wi[lane];
                int wi = warp_suffix_incl_i(wv, lane);
                s_wsuf[lane] = wi - wv;
            }
            __syncthreads();
            const int excl = (incl - tot) + s_wsuf[wid];
            if (excl < K && excl + tot >= K) {
                int cum = excl;
                #pragma unroll
                for (int j = CHB - 1; j >= 0; j--) {
                    cum += lc[j];
                    if (cum >= K) { s_tbin = base + j; break; }
                }
            }
            __syncthreads();
            const int tbin = s_tbin;

            // exact: softplus-sum above tie bin (walk own segment); gather ties
            float sa = 0.f;
            int ca = 0;
            for (int idx = lane; idx < myn; idx += 32) {
                const unsigned u = s_buf[wbase + idx];
                if (!(u & TAG)) {
                    int bin = (int)((u >> HBSHIFT) - HBASE);
                    if (bin > HBINS - 1) bin = HBINS - 1;
                    if (bin > tbin) { sa += softplus_pos(__uint_as_float(u)); ca++; }
                    else if (bin == tbin) {
                        int pi = atomicAdd(&s_tn, 1);
                        if (pi < TIE_CAP) s_tie[pi] = u;
                    }
                }
            }
            sa = warp_sum(sa);
            ca = warp_sum_i(ca);
            if (lane == 0) { s_wf[wid] = sa; s_wi[wid] = ca; }
            __syncthreads();
            if (tid == 0) {
                float fs = 0.f; int cs = 0;
                #pragma unroll
                for (int i = 0; i < NW; i++) { fs += s_wf[i]; cs += s_wi[i]; }
                int kr = K - cs;
                const int tn = s_tn;
                float tadd = 0.f;
                if (kr > 0) {
                    if (tn <= TIE_CAP) {
                        for (int a2 = 0; a2 < kr; a2++) {   // exact top-kr of tiny tie set
                            int mi = a2;
                            for (int z = a2 + 1; z < tn; z++)
                                if (s_tie[z] > s_tie[mi]) mi = z;
                            unsigned tv = s_tie[mi];
                            s_tie[mi] = s_tie[a2];
                            s_tie[a2] = tv;
                            tadd += softplus_pos(__uint_as_float(tv));
                        }
                    } else {
                        float ts = 0.f;
                        for (int z = 0; z < TIE_CAP; z++) ts += softplus_pos(__uint_as_float(s_tie[z]));
                        tadd = (float)kr * (ts / (float)TIE_CAP);
                    }
                }
                s_top = fs + tadd;
            }
            __syncthreads();
        } else {
            // ---- Exact fallback: binary search on mapped x-bits (never taken) ----
            int K_eff = NANCH - pos_num;
            if (K < K_eff) K_eff = K;
            if (K_eff > 0) {
                if (tid == 0) { s_lo = 0u; s_hi = 0xFFFFFFFFu; }
                __syncthreads();
                for (int s = 0; s < 64; s++) {
                    const unsigned lo = s_lo, hi = s_hi;
                    const unsigned w = hi - lo;
                    if (w <= 1u) break;
                    const unsigned bmid = lo + (w >> 1);
                    int c1 = 0;
                    for (int i4 = tid; i4 < NQ; i4 += T) {
                        float4 xq = pl4[i4];
                        float4 yq = gl4[i4];
                        #pragma unroll
                        for (int c = 0; c < 4; c++) {
                            float x = (c == 0) ? xq.x : (c == 1) ? xq.y : (c == 2) ? xq.z : xq.w;
                            float y = (c == 0) ? yq.x : (c == 1) ? yq.y : (c == 2) ? yq.z : yq.w;
                            if (!(y > 0.f)) c1 += (fmap(__float_as_uint(x)) >= bmid);
                        }
                    }
                    c1 = warp_sum_i(c1);
                    if (lane == 0) s_wi[wid] = c1;
                    __syncthreads();
                    if (tid == 0) {
                        int t = 0;
                        #pragma unroll
                        for (int i = 0; i < NW; i++) t += s_wi[i];
                        if (t >= K_eff) s_lo = bmid; else s_hi = bmid;
                    }
                    __syncthreads();
                }
                const unsigned lo = s_lo;
                float sa = 0.f;
                int ca = 0;
                for (int i4 = tid; i4 < NQ; i4 += T) {
                    float4 xq = pl4[i4];
                    float4 yq = gl4[i4];
                    #pragma unroll
                    for (int c = 0; c < 4; c++) {
                        float x = (c == 0) ? xq.x : (c == 1) ? xq.y : (c == 2) ? xq.z : xq.w;
                        float y = (c == 0) ? yq.x : (c == 1) ? yq.y : (c == 2) ? yq.z : yq.w;
                        if (!(y > 0.f) && fmap(__float_as_uint(x)) > lo) { sa += bce_of(x, 0.f); ca++; }
                    }
                }
                sa = warp_sum(sa);
                ca = warp_sum_i(ca);
                if (lane == 0) { s_wf[wid] = sa; s_wi[wid] = ca; }
                __syncthreads();
                if (tid == 0) {
                    float fs = 0.f; int cs = 0;
                    #pragma unroll
                    for (int i = 0; i < NW; i++) { fs += s_wf[i]; cs += s_wi[i]; }
                    float xlo = (lo & 0x80000000u) ? __uint_as_float(lo & 0x7FFFFFFFu)
                                                   : __uint_as_float(~lo);
                    s_top = fs + (float)(K_eff - cs) * bce_of(xlo, 0.f);
                }
                __syncthreads();
            }
        }
    }
    const float sum_top = (K > 0) ? s_top : 0.f;

    // ---- Publish row; last block does the final reduction ----
    if (tid == 0) {
        g_row_posn[b]  = pos_num;
        g_row_lossb[b] = s_sl1;
        g_row_lossl[b] = s_bce + sum_top;
        __threadfence();
        int prev = atomicAdd(&g_done, 1);
        s_last = (prev == BATCH - 1);
    }
    __syncthreads();

    if (s_last) {
        float vlb = 0.f, vll = 0.f, vm = 0.f;
        if (tid < BATCH) {
            float pn  = (float)((volatile int*)g_row_posn)[tid];
            float lbv = ((volatile float*)g_row_lossb)[tid];
            float llv = ((volatile float*)g_row_lossl)[tid];
            float mask = (pn > 0.f) ? 1.f : 0.f;
            float wgt  = mask / fmaxf(pn, FLT_EPS_);
            vlb = lbv * wgt;
            vll = llv * wgt;
            vm  = wgt;
        }
        vlb = warp_sum(vlb);
        vll = warp_sum(vll);
        vm  = warp_sum(vm);
        if (lane == 0) {
            s_red[wid * 3 + 0] = vlb;
            s_red[wid * 3 + 1] = vll;
            s_red[wid * 3 + 2] = vm;
        }
        __syncthreads();
        if (tid == 0) {
            float slb = 0.f, sll = 0.f, sm = 0.f;
            #pragma unroll
            for (int w = 0; w < NW; w++) {
                slb += s_red[w * 3 + 0];
                sll += s_red[w * 3 + 1];
                sm  += s_red[w * 3 + 2];
            }
            const float lb = slb / (float)BATCH;
            const float ll = sll / (float)BATCH;
            const float total = (lb + ll) * (sm / (float)BATCH);
            if (out_size >= 1) out[0] = total;
            if (out_size >= 2) out[1] = lb;
            if (out_size >= 3) out[2] = ll;
            g_done = 0;  // reset for next graph replay
        }
    }
}

extern "C" void kernel_launch(void* const* d_in, const int* in_sizes, int n_in,
                              void* d_out, int out_size) {
    const float* pbboxs  = (const float*)d_in[0];
    const float* plabels = (const float*)d_in[1];
    const float* gbboxs  = (const float*)d_in[2];
    const float* glabels = (const float*)d_in[3];
    const float* ancs    = (const float*)d_in[4];
    (void)in_sizes; (void)n_in;

    od_fused<<<BATCH, T>>>(pbboxs, plabels, gbboxs, glabels, ancs,
                           (float*)d_out, out_size);
}

// round 16
// speedup vs baseline: 5.1279x; 4.9665x over previous
#include <cuda_runtime.h>
#include <stdint.h>

#define BATCH 128
#define NANCH 16800
#define NQ 4200               // float4 per row
#define T 1024
#define NW 32
#define NIT 5                 // ceil(NQ / T)
#define NEG_RATIO 3
#define SCALE_XY 10.0f
#define SCALE_WH 5.0f
#define SEG 192               // per-warp buffer entries (exp ~98, sigma ~9.1 -> 10 sigma)
#define XCF 1.1f              // x cutoff (softplus monotone; K-th x ~1.55)
#define HBSHIFT 13
#define HBINS 4096            // bins over x in [1.0, 16.0)
#define HBASE (0x3F800000u >> HBSHIFT)
#define CHB 4                 // HBINS / T
#define TIE_CAP 64
#define TAG 0x80000000u
#define FLT_EPS_ 1.1920929e-07f

// Cross-block scratch (allocation-free rule: __device__ globals)
__device__ float g_row_lossb[BATCH];
__device__ float g_row_lossl[BATCH];
__device__ int   g_row_posn[BATCH];
__device__ int   g_done = 0;

__device__ __forceinline__ float warp_sum(float v) {
    #pragma unroll
    for (int o = 16; o > 0; o >>= 1) v += __shfl_down_sync(0xFFFFFFFFu, v, o);
    return v;
}
__device__ __forceinline__ int warp_sum_i(int v) {
    #pragma unroll
    for (int o = 16; o > 0; o >>= 1) v += __shfl_down_sync(0xFFFFFFFFu, v, o);
    return v;
}
__device__ __forceinline__ int warp_suffix_incl_i(int v, int lane) {
    #pragma unroll
    for (int o = 1; o < 32; o <<= 1) {
        int u = __shfl_down_sync(0xFFFFFFFFu, v, o);
        if (lane + o < 32) v += u;
    }
    return v;
}
__device__ __forceinline__ float bce_of(float x, float y) {
    return fmaxf(x, 0.f) - x * y + __logf(1.f + __expf(-fabsf(x)));
}
__device__ __forceinline__ float softplus_pos(float x) {   // bce for negative, x>0
    return x + __logf(1.f + __expf(-x));
}
__device__ __forceinline__ unsigned fmap(unsigned b) {     // order-preserving signed map
    return (b & 0x80000000u) ? ~b : (b | 0x80000000u);
}

__global__ __launch_bounds__(T, 1)
void od_fused(const float* __restrict__ pbboxs,
              const float* __restrict__ plabels,
              const float* __restrict__ gbboxs,
              const float* __restrict__ glabels,
              const float* __restrict__ ancs,
              float* __restrict__ out, int out_size) {
    const int b    = blockIdx.x;
    const int tid  = threadIdx.x;
    const int lane = tid & 31;
    const int wid  = tid >> 5;

    __shared__ unsigned s_buf[NW * SEG];   // per-warp tagged streams (24 KB)
    __shared__ int      s_hist[HBINS];     // 16 KB
    __shared__ unsigned s_tie[TIE_CAP];
    __shared__ float    s_wf[NW], s_wf2[NW];
    __shared__ int      s_wi[NW], s_wsuf[NW], s_wi2[NW];
    __shared__ float    s_sl1, s_bce, s_top;
    __shared__ int      s_ovf, s_tn, s_tbin, s_last;
    __shared__ unsigned s_lo, s_hi;
    __shared__ float    s_red[NW * 3];

    #pragma unroll
    for (int j = 0; j < CHB; j++) s_hist[tid + j * T] = 0;
    if (tid == 0) { s_ovf = 0; s_tn = 0; s_top = 0.f; s_tbin = 0; }
    __syncthreads();

    const float*  plr = plabels + (size_t)b * NANCH;
    const float*  glr = glabels + (size_t)b * NANCH;
    const float4* pl4 = (const float4*)plr;
    const float4* gl4 = (const float4*)glr;
    const float4* pb  = (const float4*)pbboxs + (size_t)b * NANCH;
    const float4* gb  = (const float4*)gbboxs + (size_t)b * NANCH;
    const float4* an  = (const float4*)ancs;

    // ---- Main loop: double-buffered loads; compare + ballot + rare STS ----
    // (no atomics, no shfl-broadcasts, 4 ballots/iter)
    const unsigned lm = (1u << lane) - 1u;
    const unsigned wbase = wid * SEG;
    int wcount = 0;       // warp-uniform running count of this warp's entries
    bool ovf_local = false;

    float4 xv = make_float4(0.f, 0.f, 0.f, 0.f);
    float4 yv = make_float4(0.f, 0.f, 0.f, 0.f);
    if (tid < NQ) { xv = pl4[tid]; yv = gl4[tid]; }
    #pragma unroll
    for (int it = 0; it < NIT; it++) {
        float4 xn = make_float4(0.f, 0.f, 0.f, 0.f);
        float4 yn = make_float4(0.f, 0.f, 0.f, 0.f);
        if (it + 1 < NIT) {
            const int i4n = tid + (it + 1) * T;
            if (i4n < NQ) { xn = pl4[i4n]; yn = gl4[i4n]; }
        }
        const int ei0 = (tid + it * T) << 2;
        #pragma unroll
        for (int c = 0; c < 4; c++) {
            float x = (c == 0) ? xv.x : (c == 1) ? xv.y : (c == 2) ? xv.z : xv.w;
            float y = (c == 0) ? yv.x : (c == 1) ? yv.y : (c == 2) ? yv.z : yv.w;
            const bool pos  = (y > 0.f);           // tail: y=0 -> never
            const bool intr = pos | (x >= XCF);    // tail: x=0 -> never
            unsigned msk = __ballot_sync(0xFFFFFFFFu, intr);
            if (intr) {
                const unsigned val = pos ? (TAG | (unsigned)(ei0 + c))
                                         : __float_as_uint(x);
                const int pi = wcount + __popc(msk & lm);
                if (pi < SEG) s_buf[wbase + pi] = val;
                else ovf_local = true;
            }
            wcount += __popc(msk);
        }
        xv = xn; yv = yn;
    }
    if ((lane == 0 && wcount > SEG) || ovf_local) s_ovf = 1;
    __syncthreads();

    // ---- Phase 2: each warp walks its own segment ----
    // tagged -> positive gather (batched); untagged -> histogram
    const int myn = (wcount < SEG) ? wcount : SEG;
    float acc_sl1 = 0.f, acc_bce = 0.f;
    int pcnt = 0, ccnt = 0;
    for (int idx = lane; idx < myn; idx += 32) {
        const unsigned u = s_buf[wbase + idx];
        if (u & TAG) {
            const int i = (int)(u & 0xFFFFu);
            float x = plr[i];
            float y = glr[i];
            acc_bce += bce_of(x, y);
            float4 p = pb[i];
            float4 g = gb[i];
            float4 a = an[i];
            float inv_az = 1.f / a.z;
            float inv_aw = 1.f / a.w;
            float d0 = p.x - SCALE_XY * (g.x - a.x) * inv_az;
            float d1 = p.y - SCALE_XY * (g.y - a.y) * inv_aw;
            float d2 = p.z - SCALE_WH * __logf(g.z * inv_az);
            float d3 = p.w - SCALE_WH * __logf(g.w * inv_aw);
            float ad;
            ad = fabsf(d0); acc_sl1 += (ad < 1.f) ? 0.5f * d0 * d0 : ad - 0.5f;
            ad = fabsf(d1); acc_sl1 += (ad < 1.f) ? 0.5f * d1 * d1 : ad - 0.5f;
            ad = fabsf(d2); acc_sl1 += (ad < 1.f) ? 0.5f * d2 * d2 : ad - 0.5f;
            ad = fabsf(d3); acc_sl1 += (ad < 1.f) ? 0.5f * d3 * d3 : ad - 0.5f;
            pcnt++;
        } else {
            unsigned bin = (u >> HBSHIFT) - HBASE;
            if (bin > HBINS - 1) bin = HBINS - 1;
            atomicAdd(&s_hist[bin], 1);   // spread addresses, cheap
            ccnt++;
        }
    }
    {
        float w1 = warp_sum(acc_sl1);
        float w2 = warp_sum(acc_bce);
        int   w3 = warp_sum_i(pcnt);
        int   w4 = warp_sum_i(ccnt);
        if (lane == 0) { s_wf[wid] = w1; s_wf2[wid] = w2; s_wi[wid] = w3; s_wi2[wid] = w4; }
    }
    __syncthreads();
    if (tid < 32) {
        float v1 = warp_sum(s_wf[lane]);
        float v2 = warp_sum(s_wf2[lane]);
        int   v3 = warp_sum_i(s_wi[lane]);
        int   v4 = warp_sum_i(s_wi2[lane]);
        if (lane == 0) { s_sl1 = v1; s_bce = v2; s_wi[0] = v3; s_wi2[0] = v4; }
    }
    __syncthreads();
    const int pos_num = s_wi[0];
    const int M       = s_wi2[0];
    const bool ovf    = (s_ovf != 0);
    __syncthreads();   // protect s_wi/s_wi2 reuse below

    int K = NEG_RATIO * pos_num;
    if (K > NANCH) K = NANCH;

    if (K > 0) {
        if (!ovf && M >= K) {
            // ---- Exact top-K: suffix-scan over the already-built histogram ----
            const int base = tid * CHB;
            int lc[CHB];
            int tot = 0;
            #pragma unroll
            for (int j = 0; j < CHB; j++) { lc[j] = s_hist[base + j]; tot += lc[j]; }
            int incl = warp_suffix_incl_i(tot, lane);
            if (lane == 0) s_wi[wid] = incl;
            __syncthreads();
            if (tid < 32) {
                int wv = s_wi[lane];
                int wi = warp_suffix_incl_i(wv, lane);
                s_wsuf[lane] = wi - wv;
            }
            __syncthreads();
            const int excl = (incl - tot) + s_wsuf[wid];
            if (excl < K && excl + tot >= K) {
                int cum = excl;
                #pragma unroll
                for (int j = CHB - 1; j >= 0; j--) {
                    cum += lc[j];
                    if (cum >= K) { s_tbin = base + j; break; }
                }
            }
            __syncthreads();
            const int tbin = s_tbin;

            // exact: softplus-sum above tie bin (walk own segment); gather ties
            float sa = 0.f;
            int ca = 0;
            for (int idx = lane; idx < myn; idx += 32) {
                const unsigned u = s_buf[wbase + idx];
                if (!(u & TAG)) {
                    int bin = (int)((u >> HBSHIFT) - HBASE);
                    if (bin > HBINS - 1) bin = HBINS - 1;
                    if (bin > tbin) { sa += softplus_pos(__uint_as_float(u)); ca++; }
                    else if (bin == tbin) {
                        int pi = atomicAdd(&s_tn, 1);
                        if (pi < TIE_CAP) s_tie[pi] = u;
                    }
                }
            }
            sa = warp_sum(sa);
            ca = warp_sum_i(ca);
            if (lane == 0) { s_wf[wid] = sa; s_wi[wid] = ca; }
            __syncthreads();
            if (tid == 0) {
                float fs = 0.f; int cs = 0;
                #pragma unroll
                for (int i = 0; i < NW; i++) { fs += s_wf[i]; cs += s_wi[i]; }
                int kr = K - cs;
                const int tn = s_tn;
                float tadd = 0.f;
                if (kr > 0) {
                    if (tn <= TIE_CAP) {
                        for (int a2 = 0; a2 < kr; a2++) {   // exact top-kr of tiny tie set
                            int mi = a2;
                            for (int z = a2 + 1; z < tn; z++)
                                if (s_tie[z] > s_tie[mi]) mi = z;
                            unsigned tv = s_tie[mi];
                            s_tie[mi] = s_tie[a2];
                            s_tie[a2] = tv;
                            tadd += softplus_pos(__uint_as_float(tv));
                        }
                    } else {
                        float ts = 0.f;
                        for (int z = 0; z < TIE_CAP; z++) ts += softplus_pos(__uint_as_float(s_tie[z]));
                        tadd = (float)kr * (ts / (float)TIE_CAP);
                    }
                }
                s_top = fs + tadd;
            }
            __syncthreads();
        } else {
            // ---- Exact fallback: binary search on mapped x-bits (never taken) ----
            int K_eff = NANCH - pos_num;
            if (K < K_eff) K_eff = K;
            if (K_eff > 0) {
                if (tid == 0) { s_lo = 0u; s_hi = 0xFFFFFFFFu; }
                __syncthreads();
                for (int s = 0; s < 64; s++) {
                    const unsigned lo = s_lo, hi = s_hi;
                    const unsigned w = hi - lo;
                    if (w <= 1u) break;
                    const unsigned bmid = lo + (w >> 1);
                    int c1 = 0;
                    for (int i4 = tid; i4 < NQ; i4 += T) {
                        float4 xq = pl4[i4];
                        float4 yq = gl4[i4];
                        #pragma unroll
                        for (int c = 0; c < 4; c++) {
                            float x = (c == 0) ? xq.x : (c == 1) ? xq.y : (c == 2) ? xq.z : xq.w;
                            float y = (c == 0) ? yq.x : (c == 1) ? yq.y : (c == 2) ? yq.z : yq.w;
                            if (!(y > 0.f)) c1 += (fmap(__float_as_uint(x)) >= bmid);
                        }
                    }
                    c1 = warp_sum_i(c1);
                    if (lane == 0) s_wi[wid] = c1;
                    __syncthreads();
                    if (tid == 0) {
                        int t = 0;
                        #pragma unroll
                        for (int i = 0; i < NW; i++) t += s_wi[i];
                        if (t >= K_eff) s_lo = bmid; else s_hi = bmid;
                    }
                    __syncthreads();
                }
                const unsigned lo = s_lo;
                float sa = 0.f;
                int ca = 0;
                for (int i4 = tid; i4 < NQ; i4 += T) {
                    float4 xq = pl4[i4];
                    float4 yq = gl4[i4];
                    #pragma unroll
                    for (int c = 0; c < 4; c++) {
                        float x = (c == 0) ? xq.x : (c == 1) ? xq.y : (c == 2) ? xq.z : xq.w;
                        float y = (c == 0) ? yq.x : (c == 1) ? yq.y : (c == 2) ? yq.z : yq.w;
                        if (!(y > 0.f) && fmap(__float_as_uint(x)) > lo) { sa += bce_of(x, 0.f); ca++; }
                    }
                }
                sa = warp_sum(sa);
                ca = warp_sum_i(ca);
                if (lane == 0) { s_wf[wid] = sa; s_wi[wid] = ca; }
                __syncthreads();
                if (tid == 0) {
                    float fs = 0.f; int cs = 0;
                    #pragma unroll
                    for (int i = 0; i < NW; i++) { fs += s_wf[i]; cs += s_wi[i]; }
                    float xlo = (lo & 0x80000000u) ? __uint_as_float(lo & 0x7FFFFFFFu)
                                                   : __uint_as_float(~lo);
                    s_top = fs + (float)(K_eff - cs) * bce_of(xlo, 0.f);
                }
                __syncthreads();
            }
        }
    }
    const float sum_top = (K > 0) ? s_top : 0.f;

    // ---- Publish row; last block does the final reduction ----
    if (tid == 0) {
        g_row_posn[b]  = pos_num;
        g_row_lossb[b] = s_sl1;
        g_row_lossl[b] = s_bce + sum_top;
        __threadfence();
        int prev = atomicAdd(&g_done, 1);
        s_last = (prev == BATCH - 1);
    }
    __syncthreads();

    if (s_last) {
        float vlb = 0.f, vll = 0.f, vm = 0.f;
        if (tid < BATCH) {
            float pn  = (float)((volatile int*)g_row_posn)[tid];
            float lbv = ((volatile float*)g_row_lossb)[tid];
            float llv = ((volatile float*)g_row_lossl)[tid];
            float mask = (pn > 0.f) ? 1.f : 0.f;
            float wgt  = mask / fmaxf(pn, FLT_EPS_);
            vlb = lbv * wgt;
            vll = llv * wgt;
            vm  = wgt;
        }
        vlb = warp_sum(vlb);
        vll = warp_sum(vll);
        vm  = warp_sum(vm);
        if (lane == 0) {
            s_red[wid * 3 + 0] = vlb;
            s_red[wid * 3 + 1] = vll;
            s_red[wid * 3 + 2] = vm;
        }
        __syncthreads();
        if (tid == 0) {
            float slb = 0.f, sll = 0.f, sm = 0.f;
            #pragma unroll
            for (int w = 0; w < NW; w++) {
                slb += s_red[w * 3 + 0];
                sll += s_red[w * 3 + 1];
                sm  += s_red[w * 3 + 2];
            }
            const float lb = slb / (float)BATCH;
            const float ll = sll / (float)BATCH;
            const float total = (lb + ll) * (sm / (float)BATCH);
            if (out_size >= 1) out[0] = total;
            if (out_size >= 2) out[1] = lb;
            if (out_size >= 3) out[2] = ll;
            g_done = 0;  // reset for next graph replay
        }
    }
}

extern "C" void kernel_launch(void* const* d_in, const int* in_sizes, int n_in,
                              void* d_out, int out_size) {
    const float* pbboxs  = (const float*)d_in[0];
    const float* plabels = (const float*)d_in[1];
    const float* gbboxs  = (const float*)d_in[2];
    const float* glabels = (const float*)d_in[3];
    const float* ancs    = (const float*)d_in[4];
    (void)in_sizes; (void)n_in;

    od_fused<<<BATCH, T>>>(pbboxs, plabels, gbboxs, glabels, ancs,
                           (float*)d_out, out_size);
}